// round 4
// baseline (speedup 1.0000x reference)
#include <cuda_runtime.h>
#include <math.h>
#include <stdint.h>

#define BB 2048
#define SS 200
#define DD 192
#define H1 64
#define H2 32
#define NT 512
#define KT 32
#define NTILE 6
#define APAD 204   // transposed A-tile row stride (floats); %4==0 for LDS.128 align

typedef unsigned long long ull;

// ---- smem layout (floats) ----
#define SM_WEFFD 0                          // [192][128] duplicated pairs = 24576
#define SM_ABUF  (SM_WEFFD + 24576)         // 2 * KT * APAD = 13056 ; overlaid by H[200][64] after GEMM
#define SM_QS    (SM_ABUF + 2*KT*APAD)      // 192
#define SM_B1    (SM_QS + 192)              // 64
#define SM_W2    (SM_B1 + 64)               // 2048 [h][k]
#define SM_W3    (SM_W2 + 2048)             // 32
#define SM_B2    (SM_W3 + 32)               // 32
#define SM_SC    (SM_B2 + 32)               // 256
#define SM_WGT   (SM_SC + 256)              // 256
#define SM_RED   (SM_WGT + 256)             // 512
#define SMEM_FLOATS (SM_RED + 512)          // 41024 floats = 164096 B

__device__ __forceinline__ void cp4(uint32_t dst, const float* src) {
    asm volatile("cp.async.ca.shared.global [%0], [%1], 4;" :: "r"(dst), "l"(src));
}
__device__ __forceinline__ void cp_commit() { asm volatile("cp.async.commit_group;" ::: "memory"); }
__device__ __forceinline__ void cp_wait1()  { asm volatile("cp.async.wait_group 1;" ::: "memory"); }
__device__ __forceinline__ void cp_wait0()  { asm volatile("cp.async.wait_group 0;" ::: "memory"); }

__device__ __forceinline__ ull pk2(float x) {
    ull r; asm("mov.b64 %0, {%1, %1};" : "=l"(r) : "f"(x)); return r;
}
__device__ __forceinline__ void fma2(ull& d, ull a, ull b) {
    asm("fma.rn.f32x2 %0, %1, %2, %0;" : "+l"(d) : "l"(a), "l"(b));
}
__device__ __forceinline__ float2 up2(ull v) {
    float2 r; asm("mov.b64 {%0, %1}, %2;" : "=f"(r.x), "=f"(r.y) : "l"(v)); return r;
}

__global__ __launch_bounds__(NT, 1)
void rich_attn_kernel(const float* __restrict__ query,
                      const float* __restrict__ keys,
                      const int*   __restrict__ kmask,
                      const float* __restrict__ W1,
                      const float* __restrict__ b1,
                      const float* __restrict__ a1p,
                      const float* __restrict__ W2,
                      const float* __restrict__ b2,
                      const float* __restrict__ a2p,
                      const float* __restrict__ W3,
                      const float* __restrict__ b3p,
                      float* __restrict__ out)
{
    extern __shared__ float sm[];
    const int tid = threadIdx.x;
    const int b   = blockIdx.x;

    const float a1 = a1p[0];
    const float a2 = a2p[0];
    const float b3 = b3p[0];

    const float* kbase = keys + (size_t)b * SS * DD;
    uint32_t smem_u32 = (uint32_t)__cvta_generic_to_shared((void*)sm);

    // ---------- prefetch keys tiles 0,1 (transposed: As[k][s]) ----------
    #pragma unroll
    for (int t = 0; t < 2; t++) {
        const float* g = kbase + t * KT;
        uint32_t abase = smem_u32 + (SM_ABUF + t * KT * APAD) * 4;
        for (int e = tid; e < SS * KT; e += NT) {
            int s = e >> 5;
            int k = e & 31;
            cp4(abase + (uint32_t)(k * APAD + s) * 4, g + (size_t)s * DD + k);
        }
        cp_commit();
    }

    float* weffd = sm + SM_WEFFD;
    float* qs    = sm + SM_QS;
    float* bias1 = sm + SM_B1;
    float* w2s   = sm + SM_W2;
    float* w3s   = sm + SM_W3;
    float* b2s   = sm + SM_B2;
    float* score = sm + SM_SC;
    float* wgt   = sm + SM_WGT;
    float* red   = sm + SM_RED;

    if (tid < DD) qs[tid] = query[(size_t)b * DD + tid];
    for (int idx = tid; idx < H1 * H2; idx += NT) w2s[idx] = W2[idx];
    if (tid < H2) { w3s[tid] = W3[tid]; b2s[tid] = b2[tid]; }
    if (tid < 256) { score[tid] = -INFINITY; wgt[tid] = 0.f; }
    __syncthreads();   // qs ready

    // ---------- weffd[i][2h],[2h+1] = W1[i,h] + W1[576+i,h] + q_i*W1[384+i,h] ----------
    for (int idx = tid; idx < DD * H1; idx += NT) {
        int i = idx >> 6;
        int h = idx & 63;
        float v = W1[idx] + W1[(576 + i) * H1 + h] + qs[i] * W1[(384 + i) * H1 + h];
        ull vv = pk2(v);
        *reinterpret_cast<ull*>(weffd + (size_t)i * 128 + 2 * h) = vv;
    }
    // ---------- bias1[h] = b1[h] + sum_i q_i*(W1[192+i,h]-W1[576+i,h]) ----------
    {
        int h = tid & 63;
        int c = tid >> 6;                 // 0..7 chunks of 24
        float acc = 0.f;
        int i0 = c * 24;
        #pragma unroll 4
        for (int i = i0; i < i0 + 24; i++)
            acc = fmaf(qs[i], W1[(192 + i) * H1 + h] - W1[(576 + i) * H1 + h], acc);
        red[tid] = acc;
    }
    __syncthreads();
    if (tid < H1) {
        float acc = b1[tid];
        #pragma unroll
        for (int c = 0; c < 8; c++) acc += red[tid + 64 * c];
        bias1[tid] = acc;
    }
    __syncthreads();

    // ---------- GEMM: H(200x64) = keys(200x192) @ weff(192x64), s-paired f32x2 ----------
    const int sg = tid >> 4;          // 0..31 (0..24 active)
    const int hg = tid & 15;          // 0..15
    const int s0 = sg * 8;
    const int h0 = hg * 4;
    const bool comp = (sg < 25);

    ull acc[4][4];                    // [s-pair][h]
    if (comp) {
        #pragma unroll
        for (int hh = 0; hh < 4; hh++) {
            ull bi = pk2(bias1[h0 + hh]);
            #pragma unroll
            for (int p = 0; p < 4; p++) acc[p][hh] = bi;
        }
    }

    for (int t = 0; t < NTILE; t++) {
        if (t == NTILE - 1) cp_wait0(); else cp_wait1();
        __syncthreads();

        if (comp) {
            const float* At = sm + SM_ABUF + (t & 1) * KT * APAD + s0;
            const float* Wd = weffd + (size_t)t * KT * 128 + 2 * h0;
            #pragma unroll 8
            for (int k = 0; k < KT; k++) {
                ulonglong2 a01 = *reinterpret_cast<const ulonglong2*>(At + k * APAD);
                ulonglong2 a23 = *reinterpret_cast<const ulonglong2*>(At + k * APAD + 4);
                ulonglong2 b01 = *reinterpret_cast<const ulonglong2*>(Wd + (size_t)k * 128);
                ulonglong2 b23 = *reinterpret_cast<const ulonglong2*>(Wd + (size_t)k * 128 + 4);
                ull ap[4] = {a01.x, a01.y, a23.x, a23.y};
                ull bp[4] = {b01.x, b01.y, b23.x, b23.y};
                #pragma unroll
                for (int p = 0; p < 4; p++) {
                    fma2(acc[p][0], ap[p], bp[0]);
                    fma2(acc[p][1], ap[p], bp[1]);
                    fma2(acc[p][2], ap[p], bp[2]);
                    fma2(acc[p][3], ap[p], bp[3]);
                }
            }
        }
        __syncthreads();

        if (t + 2 < NTILE) {
            const float* g = kbase + (t + 2) * KT;
            uint32_t abase = smem_u32 + (SM_ABUF + (t & 1) * KT * APAD) * 4;
            for (int e = tid; e < SS * KT; e += NT) {
                int s = e >> 5;
                int k = e & 31;
                cp4(abase + (uint32_t)(k * APAD + s) * 4, g + (size_t)s * DD + k);
            }
            cp_commit();
        }
    }

    // ---------- prelu1 + store H[200][64] (overlay A buffers) ----------
    float* Hs = sm + SM_ABUF;
    if (comp) {
        #pragma unroll
        for (int p = 0; p < 4; p++) {
            int sA = s0 + 2 * p;
            #pragma unroll
            for (int hh = 0; hh < 4; hh++) {
                float2 v = up2(acc[p][hh]);
                float v0 = (v.x >= 0.f) ? v.x : a1 * v.x;
                float v1 = (v.y >= 0.f) ? v.y : a1 * v.y;
                Hs[(size_t)sA * H1 + h0 + hh]       = v0;
                Hs[(size_t)(sA + 1) * H1 + h0 + hh] = v1;
            }
        }
    }
    __syncthreads();

    // ---------- layers 2+3 per s ----------
    if (tid < SS) {
        const float* hrow = Hs + (size_t)tid * H1;
        ull acc2[16];
        {
            const ulonglong2* bp = reinterpret_cast<const ulonglong2*>(b2s);
            #pragma unroll
            for (int j = 0; j < 8; j++) { acc2[2*j] = bp[j].x; acc2[2*j+1] = bp[j].y; }
        }
        #pragma unroll 4
        for (int h = 0; h < H1; h++) {
            ull xx = pk2(hrow[h]);
            const ulonglong2* wr = reinterpret_cast<const ulonglong2*>(w2s + h * H2);
            #pragma unroll
            for (int j4 = 0; j4 < 8; j4++) {
                ulonglong2 wv = wr[j4];
                fma2(acc2[2*j4],   xx, wv.x);
                fma2(acc2[2*j4+1], xx, wv.y);
            }
        }
        float sc = b3;
        #pragma unroll
        for (int j = 0; j < 16; j++) {
            float2 p = up2(acc2[j]);
            float v0 = (p.x >= 0.f) ? p.x : a2 * p.x;
            float v1 = (p.y >= 0.f) ? p.y : a2 * p.y;
            sc = fmaf(v0, w3s[2*j], sc);
            sc = fmaf(v1, w3s[2*j + 1], sc);
        }
        int mv = kmask[(size_t)b * SS + tid];
        score[tid] = mv ? sc : -INFINITY;
    }
    __syncthreads();

    // ---------- softmax over 256-padded score ----------
    if (tid < 256) red[tid] = score[tid];
    __syncthreads();
    #pragma unroll
    for (int off = 128; off > 0; off >>= 1) {
        if (tid < off) red[tid] = fmaxf(red[tid], red[tid + off]);
        __syncthreads();
    }
    const float m = red[0];
    __syncthreads();

    float e = 0.f;
    if (tid < SS && m > -INFINITY) {
        float svv = score[tid];
        e = (svv > -INFINITY) ? expf(svv - m) : 0.f;
    }
    if (tid < 256) red[tid] = e;
    __syncthreads();
    #pragma unroll
    for (int off = 128; off > 0; off >>= 1) {
        if (tid < off) red[tid] += red[tid + off];
        __syncthreads();
    }
    const float ssum = red[0];
    __syncthreads();
    const float inv = (ssum > 0.f) ? (1.f / ssum) : 0.f;

    if (tid < 256) {
        float wv = e * inv;
        wgt[tid] = wv;
        if (tid < SS) out[(size_t)BB * DD + (size_t)b * SS + tid] = wv;
    }
    __syncthreads();

    // ---------- weighted sum: out[b,d] = sum_s wgt[s]*keys[b,s,d], split in 2 s-halves ----------
    if (tid < 2 * DD) {
        int half = (tid >= DD);
        int d = tid - half * DD;
        const float* kb = kbase + (size_t)(half * 100) * DD + d;
        const float* wp = wgt + half * 100;
        float accw = 0.f;
        #pragma unroll 5
        for (int si = 0; si < 100; si++)
            accw = fmaf(wp[si], kb[(size_t)si * DD], accw);
        red[tid] = accw;
    }
    __syncthreads();
    if (tid < DD) out[(size_t)b * DD + tid] = red[tid] + red[tid + DD];
}

extern "C" void kernel_launch(void* const* d_in, const int* in_sizes, int n_in,
                              void* d_out, int out_size)
{
    const float* query = (const float*)d_in[0];
    const float* keys  = (const float*)d_in[1];
    const int*   mask  = (const int*)  d_in[2];
    const float* W1    = (const float*)d_in[3];
    const float* b1    = (const float*)d_in[4];
    const float* a1    = (const float*)d_in[5];
    const float* W2    = (const float*)d_in[6];
    const float* b2    = (const float*)d_in[7];
    const float* a2    = (const float*)d_in[8];
    const float* W3    = (const float*)d_in[9];
    const float* b3    = (const float*)d_in[10];
    float* out = (float*)d_out;

    static bool attr_set = false;
    if (!attr_set) {
        cudaFuncSetAttribute(rich_attn_kernel,
                             cudaFuncAttributeMaxDynamicSharedMemorySize,
                             SMEM_FLOATS * sizeof(float));
        attr_set = true;
    }

    rich_attn_kernel<<<BB, NT, SMEM_FLOATS * sizeof(float)>>>(
        query, keys, mask, W1, b1, a1, W2, b2, a2, W3, b3, out);
}

// round 5
// speedup vs baseline: 1.2594x; 1.2594x over previous
#include <cuda_runtime.h>
#include <math.h>
#include <stdint.h>

#define BB 2048
#define SS 200
#define DD 192
#define H1 64
#define H2 32
#define NT 512
#define KT 32
#define NTILE 6
#define APAD 204     // transposed A-tile row stride (floats), %4==0
#define BPAD 136     // weffd row stride (floats)
#define HPADR 68     // Hs row stride

typedef unsigned long long ull;

// ---- smem layout (floats) ----
#define SM_WEFFD 0                            // 192*136 = 26112
#define SM_ABUF  26112                        // 2*KT*APAD = 13056 (+qs+b1+pad overlaid by Hs=200*68=13600)
#define SM_QS    (SM_ABUF + 13056)            // 192   (dead after weffd build)
#define SM_B1    (SM_QS + 192)                // 64    (dead after acc init)
#define SM_HPAD  (SM_B1 + 64)                 // 288   (Hs overflow room)
#define SM_W2    (SM_HPAD + 288)              // 2048 [h][k]
#define SM_W3    (SM_W2 + 2048)               // 32
#define SM_B2    (SM_W3 + 32)                 // 32
#define SM_SC    (SM_B2 + 32)                 // 256
#define SM_WGT   (SM_SC + 256)                // 256
#define SM_RED   (SM_WGT + 256)               // 512
#define SMEM_FLOATS (SM_RED + 512)            // 42848 floats = 171392 B

__device__ __forceinline__ ull pk2(float x) {
    ull r; asm("mov.b64 %0, {%1, %1};" : "=l"(r) : "f"(x)); return r;
}
__device__ __forceinline__ void fma2(ull& d, ull a, ull b) {
    asm("fma.rn.f32x2 %0, %1, %2, %0;" : "+l"(d) : "l"(a), "l"(b));
}
__device__ __forceinline__ float2 up2(ull v) {
    float2 r; asm("mov.b64 {%0, %1}, %2;" : "=f"(r.x), "=f"(r.y) : "l"(v)); return r;
}

__global__ __launch_bounds__(NT, 1)
void rich_attn_kernel(const float* __restrict__ query,
                      const float* __restrict__ keys,
                      const int*   __restrict__ kmask,
                      const float* __restrict__ W1,
                      const float* __restrict__ b1,
                      const float* __restrict__ a1p,
                      const float* __restrict__ W2,
                      const float* __restrict__ b2,
                      const float* __restrict__ a2p,
                      const float* __restrict__ W3,
                      const float* __restrict__ b3p,
                      float* __restrict__ out)
{
    extern __shared__ float sm[];
    const int tid = threadIdx.x;
    const int b   = blockIdx.x;

    const float a1 = a1p[0];
    const float a2 = a2p[0];
    const float b3 = b3p[0];

    const float* kbase = keys + (size_t)b * SS * DD;

    float* weffd = sm + SM_WEFFD;
    float* qs    = sm + SM_QS;
    float* bias1 = sm + SM_B1;
    float* w2s   = sm + SM_W2;
    float* w3s   = sm + SM_W3;
    float* b2s   = sm + SM_B2;
    float* score = sm + SM_SC;
    float* wgt   = sm + SM_WGT;
    float* red   = sm + SM_RED;

    // loader mapping: f in [0,1600): s = f>>3, kq = f&7 -> float4 keys[s][tcol+4kq..+3]
    const int lf_s  = tid >> 3;          // s for f=tid
    const int lf_kq = tid & 7;

    // ---- tile 0: LDG + STS (prologue) ----
    float4 r0, r1, r2, r3;
    {
        const float* g = kbase;
        r0 = *reinterpret_cast<const float4*>(g + (size_t)lf_s * DD + 4 * lf_kq);
        r1 = *reinterpret_cast<const float4*>(g + (size_t)(lf_s + 64) * DD + 4 * lf_kq);
        r2 = *reinterpret_cast<const float4*>(g + (size_t)(lf_s + 128) * DD + 4 * lf_kq);
        if (tid < 64)
            r3 = *reinterpret_cast<const float4*>(g + (size_t)(lf_s + 192) * DD + 4 * lf_kq);
    }
    {
        float* A0 = sm + SM_ABUF;
        int kk = 4 * lf_kq;
        A0[(kk+0)*APAD + lf_s] = r0.x; A0[(kk+1)*APAD + lf_s] = r0.y;
        A0[(kk+2)*APAD + lf_s] = r0.z; A0[(kk+3)*APAD + lf_s] = r0.w;
        A0[(kk+0)*APAD + lf_s+64] = r1.x; A0[(kk+1)*APAD + lf_s+64] = r1.y;
        A0[(kk+2)*APAD + lf_s+64] = r1.z; A0[(kk+3)*APAD + lf_s+64] = r1.w;
        A0[(kk+0)*APAD + lf_s+128] = r2.x; A0[(kk+1)*APAD + lf_s+128] = r2.y;
        A0[(kk+2)*APAD + lf_s+128] = r2.z; A0[(kk+3)*APAD + lf_s+128] = r2.w;
        if (tid < 64) {
            A0[(kk+0)*APAD + lf_s+192] = r3.x; A0[(kk+1)*APAD + lf_s+192] = r3.y;
            A0[(kk+2)*APAD + lf_s+192] = r3.z; A0[(kk+3)*APAD + lf_s+192] = r3.w;
        }
    }
    // ---- issue LDG for tile 1 ----
    {
        const float* g = kbase + KT;
        r0 = *reinterpret_cast<const float4*>(g + (size_t)lf_s * DD + 4 * lf_kq);
        r1 = *reinterpret_cast<const float4*>(g + (size_t)(lf_s + 64) * DD + 4 * lf_kq);
        r2 = *reinterpret_cast<const float4*>(g + (size_t)(lf_s + 128) * DD + 4 * lf_kq);
        if (tid < 64)
            r3 = *reinterpret_cast<const float4*>(g + (size_t)(lf_s + 192) * DD + 4 * lf_kq);
    }

    // ---- q + small weights ----
    if (tid < DD) qs[tid] = query[(size_t)b * DD + tid];
    for (int idx = tid; idx < H1 * H2; idx += NT) w2s[idx] = W2[idx];
    if (tid < H2) { w3s[tid] = W3[tid]; b2s[tid] = b2[tid]; }
    if (tid >= 256 && tid < 512) { score[tid - 256] = -INFINITY; wgt[tid - 256] = 0.f; }
    __syncthreads();   // qs ready; tile-0 STS done

    // ---- weffd: duplicated interleaved layout ----
    // addr(i,h) = i*BPAD + ((h>>1)&1)*64 + (h>>2)*4 + 2*(h&1), value = pk2(weff[i][h])
    for (int idx = tid; idx < DD * H1; idx += NT) {
        int i = idx >> 6;
        int h = idx & 63;
        float v = W1[idx] + W1[(576 + i) * H1 + h] + qs[i] * W1[(384 + i) * H1 + h];
        int addr = i * BPAD + ((h >> 1) & 1) * 64 + (h >> 2) * 4 + 2 * (h & 1);
        *reinterpret_cast<ull*>(weffd + addr) = pk2(v);
    }
    // ---- bias1 ----
    {
        int h = tid & 63;
        int c = tid >> 6;                 // 0..7 chunks of 24
        float acc = 0.f;
        int i0 = c * 24;
        #pragma unroll 4
        for (int i = i0; i < i0 + 24; i++)
            acc = fmaf(qs[i], W1[(192 + i) * H1 + h] - W1[(576 + i) * H1 + h], acc);
        red[tid] = acc;
    }
    __syncthreads();
    if (tid < H1) {
        float acc = b1[tid];
        #pragma unroll
        for (int c = 0; c < 8; c++) acc += red[tid + 64 * c];
        bias1[tid] = acc;
    }
    __syncthreads();

    // ---- GEMM: 400 comp threads, tile 8s x 4h, s-paired f32x2 ----
    const int sg = tid >> 4;          // 0..31 (0..24 active)
    const int hg = tid & 15;          // 0..15
    const int s0 = sg * 8;
    const bool comp = (sg < 25);

    ull acc[4][4];                    // [s-pair][hh], h = 4*hg + hh
    if (comp) {
        #pragma unroll
        for (int hh = 0; hh < 4; hh++) {
            ull bi = pk2(bias1[4 * hg + hh]);
            #pragma unroll
            for (int p = 0; p < 4; p++) acc[p][hh] = bi;
        }
    }

    for (int t = 0; t < NTILE; t++) {
        // compute tile t
        if (comp) {
            const float* At = sm + SM_ABUF + (t & 1) * KT * APAD + s0;
            const float* Wd = weffd + (size_t)t * KT * BPAD + hg * 4;
            #pragma unroll 8
            for (int k = 0; k < KT; k++) {
                ulonglong2 a01 = *reinterpret_cast<const ulonglong2*>(At + k * APAD);
                ulonglong2 a23 = *reinterpret_cast<const ulonglong2*>(At + k * APAD + 4);
                ulonglong2 bc0 = *reinterpret_cast<const ulonglong2*>(Wd + k * BPAD);
                ulonglong2 bc1 = *reinterpret_cast<const ulonglong2*>(Wd + k * BPAD + 64);
                ull ap[4] = {a01.x, a01.y, a23.x, a23.y};
                ull bp[4] = {bc0.x, bc0.y, bc1.x, bc1.y};
                #pragma unroll
                for (int p = 0; p < 4; p++) {
                    fma2(acc[p][0], ap[p], bp[0]);
                    fma2(acc[p][1], ap[p], bp[1]);
                    fma2(acc[p][2], ap[p], bp[2]);
                    fma2(acc[p][3], ap[p], bp[3]);
                }
            }
        }
        __syncthreads();   // everyone done reading buf[(t+1)&1] (from tile t-1)

        if (t + 1 < NTILE) {
            // STS tile t+1 (regs) into buf[(t+1)&1]
            float* A0 = sm + SM_ABUF + ((t + 1) & 1) * KT * APAD;
            int kk = 4 * lf_kq;
            A0[(kk+0)*APAD + lf_s] = r0.x; A0[(kk+1)*APAD + lf_s] = r0.y;
            A0[(kk+2)*APAD + lf_s] = r0.z; A0[(kk+3)*APAD + lf_s] = r0.w;
            A0[(kk+0)*APAD + lf_s+64] = r1.x; A0[(kk+1)*APAD + lf_s+64] = r1.y;
            A0[(kk+2)*APAD + lf_s+64] = r1.z; A0[(kk+3)*APAD + lf_s+64] = r1.w;
            A0[(kk+0)*APAD + lf_s+128] = r2.x; A0[(kk+1)*APAD + lf_s+128] = r2.y;
            A0[(kk+2)*APAD + lf_s+128] = r2.z; A0[(kk+3)*APAD + lf_s+128] = r2.w;
            if (tid < 64) {
                A0[(kk+0)*APAD + lf_s+192] = r3.x; A0[(kk+1)*APAD + lf_s+192] = r3.y;
                A0[(kk+2)*APAD + lf_s+192] = r3.z; A0[(kk+3)*APAD + lf_s+192] = r3.w;
            }
            if (t + 2 < NTILE) {
                const float* g = kbase + (t + 2) * KT;
                r0 = *reinterpret_cast<const float4*>(g + (size_t)lf_s * DD + 4 * lf_kq);
                r1 = *reinterpret_cast<const float4*>(g + (size_t)(lf_s + 64) * DD + 4 * lf_kq);
                r2 = *reinterpret_cast<const float4*>(g + (size_t)(lf_s + 128) * DD + 4 * lf_kq);
                if (tid < 64)
                    r3 = *reinterpret_cast<const float4*>(g + (size_t)(lf_s + 192) * DD + 4 * lf_kq);
            }
        }
        __syncthreads();   // buf[(t+1)&1] ready
    }

    // ---- prelu1 + store H[s][64] (pad 68) overlaying Abuf ----
    float* Hs = sm + SM_ABUF;
    if (comp) {
        #pragma unroll
        for (int p = 0; p < 4; p++) {
            int sA = s0 + 2 * p;
            #pragma unroll
            for (int hh = 0; hh < 4; hh++) {
                float2 v = up2(acc[p][hh]);
                float v0 = (v.x >= 0.f) ? v.x : a1 * v.x;
                float v1 = (v.y >= 0.f) ? v.y : a1 * v.y;
                Hs[sA * HPADR + 4 * hg + hh]       = v0;
                Hs[(sA + 1) * HPADR + 4 * hg + hh] = v1;
            }
        }
    }
    __syncthreads();

    // ---- layers 2+3 per s ----
    if (tid < SS) {
        const float* hrow = Hs + tid * HPADR;
        ull acc2[16];
        {
            const ulonglong2* bp = reinterpret_cast<const ulonglong2*>(b2s);
            #pragma unroll
            for (int j = 0; j < 8; j++) { acc2[2*j] = bp[j].x; acc2[2*j+1] = bp[j].y; }
        }
        #pragma unroll 8
        for (int h = 0; h < H1; h++) {
            ull xx = pk2(hrow[h]);
            const ulonglong2* wr = reinterpret_cast<const ulonglong2*>(w2s + h * H2);
            #pragma unroll
            for (int j4 = 0; j4 < 8; j4++) {
                ulonglong2 wv = wr[j4];
                fma2(acc2[2*j4],   xx, wv.x);
                fma2(acc2[2*j4+1], xx, wv.y);
            }
        }
        float sc = b3;
        #pragma unroll
        for (int j = 0; j < 16; j++) {
            float2 p = up2(acc2[j]);
            float v0 = (p.x >= 0.f) ? p.x : a2 * p.x;
            float v1 = (p.y >= 0.f) ? p.y : a2 * p.y;
            sc = fmaf(v0, w3s[2*j], sc);
            sc = fmaf(v1, w3s[2*j + 1], sc);
        }
        int mv = kmask[(size_t)b * SS + tid];
        score[tid] = mv ? sc : -INFINITY;
    }
    __syncthreads();

    // ---- softmax over 256-padded score ----
    if (tid < 256) red[tid] = score[tid];
    __syncthreads();
    #pragma unroll
    for (int off = 128; off > 0; off >>= 1) {
        if (tid < off) red[tid] = fmaxf(red[tid], red[tid + off]);
        __syncthreads();
    }
    const float m = red[0];
    __syncthreads();

    float e = 0.f;
    if (tid < SS && m > -INFINITY) {
        float svv = score[tid];
        e = (svv > -INFINITY) ? expf(svv - m) : 0.f;
    }
    if (tid < 256) red[tid] = e;
    __syncthreads();
    #pragma unroll
    for (int off = 128; off > 0; off >>= 1) {
        if (tid < off) red[tid] += red[tid + off];
        __syncthreads();
    }
    const float ssum = red[0];
    __syncthreads();
    const float inv = (ssum > 0.f) ? (1.f / ssum) : 0.f;

    if (tid < 256) {
        float wv = e * inv;
        wgt[tid] = wv;
        if (tid < SS) out[(size_t)BB * DD + (size_t)b * SS + tid] = wv;
    }
    __syncthreads();

    // ---- weighted sum: out[b,d] = sum_s wgt[s]*keys[b,s,d], 2 s-halves ----
    if (tid < 2 * DD) {
        int half = (tid >= DD);
        int d = tid - half * DD;
        const float* kb = kbase + (size_t)(half * 100) * DD + d;
        const float* wp = wgt + half * 100;
        float accw = 0.f;
        #pragma unroll 5
        for (int si = 0; si < 100; si++)
            accw = fmaf(wp[si], kb[(size_t)si * DD], accw);
        red[tid] = accw;
    }
    __syncthreads();
    if (tid < DD) out[(size_t)b * DD + tid] = red[tid] + red[tid + DD];
}

extern "C" void kernel_launch(void* const* d_in, const int* in_sizes, int n_in,
                              void* d_out, int out_size)
{
    const float* query = (const float*)d_in[0];
    const float* keys  = (const float*)d_in[1];
    const int*   mask  = (const int*)  d_in[2];
    const float* W1    = (const float*)d_in[3];
    const float* b1    = (const float*)d_in[4];
    const float* a1    = (const float*)d_in[5];
    const float* W2    = (const float*)d_in[6];
    const float* b2    = (const float*)d_in[7];
    const float* a2    = (const float*)d_in[8];
    const float* W3    = (const float*)d_in[9];
    const float* b3    = (const float*)d_in[10];
    float* out = (float*)d_out;

    static bool attr_set = false;
    if (!attr_set) {
        cudaFuncSetAttribute(rich_attn_kernel,
                             cudaFuncAttributeMaxDynamicSharedMemorySize,
                             SMEM_FLOATS * sizeof(float));
        attr_set = true;
    }

    rich_attn_kernel<<<BB, NT, SMEM_FLOATS * sizeof(float)>>>(
        query, keys, mask, W1, b1, a1, W2, b2, a2, W3, b3, out);
}